// round 2
// baseline (speedup 1.0000x reference)
#include <cuda_runtime.h>
#include <math.h>

#define BATCH 8192
#define SEQ 64
#define FEAT 65
#define HID 128
#define G3 384
#define DZ 64

// ---------------- scratch (device globals; no allocation allowed) ----------
__device__ float  d_HtH[BATCH*64*64];          // 134 MB
__device__ float  d_Hty[BATCH*64];             // 2 MB
__device__ double d_stats[128];                // per-channel sum / sumsq
__device__ float  d_scale[64];
__device__ float  d_shift[64];
__device__ float  d_wsum[2*G3];
__device__ float  d_xg[402653184];             // (2*SEQ*BATCH*G3) 1.61 GB
__device__ float  d_h[2][2*BATCH*HID];         // ping-pong hidden state
__device__ float  d_hg[2*BATCH*G3];            // per-step hidden gates
__device__ float  d_go[134217728];             // (BATCH*SEQ*256) 537 MB
__device__ float  d_wx[BATCH*SEQ*DZ];          // 134 MB
__device__ float  d_gx[BATCH*256];

// ---------------- init: zero stats + h0 ------------------------------------
__global__ __launch_bounds__(256) void k_init() {
    int idx = blockIdx.x*256 + threadIdx.x;
    if (idx < 2*BATCH*HID) d_h[0][idx] = 0.f;
    if (blockIdx.x == 0 && threadIdx.x < 128) d_stats[threadIdx.x] = 0.0;
}

// ---------------- per-batch HtH, Hty + BN partial stats ---------------------
__global__ __launch_bounds__(256) void k_hth(const float* __restrict__ Hg,
                                             const float* __restrict__ yg) {
    int b = blockIdx.x;
    __shared__ float Hs[64][65];
    __shared__ float ys[64];
    __shared__ float hty[64];
    __shared__ float csum[64];
    __shared__ float csq[64];
    int tid = threadIdx.x;
    const float* Hb = Hg + (size_t)b*4096;
    for (int i = tid; i < 4096; i += 256) Hs[i>>6][i&63] = Hb[i];
    if (tid < 64) { ys[tid] = yg[b*64+tid]; csum[tid]=0.f; csq[tid]=0.f; }
    __syncthreads();
    if (tid < 64) {
        float a = 0.f;
#pragma unroll
        for (int r=0;r<64;r++) a += Hs[r][tid]*ys[r];
        hty[tid] = a;
        d_Hty[b*64+tid] = a;
    }
    __syncthreads();
    float* outp = d_HtH + (size_t)b*4096;
    int lane = tid & 31;
#pragma unroll 4
    for (int kk=0; kk<16; kk++) {
        int i = tid + kk*256;
        int t = i>>6, u = i&63;
        float a = 0.f;
#pragma unroll
        for (int r=0;r<64;r++) a += Hs[r][t]*Hs[r][u];
        outp[i] = a;
        float s1 = a, s2 = a*a;
#pragma unroll
        for (int o=16;o>0;o>>=1) {
            s1 += __shfl_down_sync(0xffffffffu, s1, o);
            s2 += __shfl_down_sync(0xffffffffu, s2, o);
        }
        if (lane==0) { atomicAdd(&csum[t], s1); atomicAdd(&csq[t], s2); }
    }
    __syncthreads();
    if (tid < 64) {
        float v = hty[tid];
        atomicAdd(&d_stats[tid],      (double)(csum[tid]+v));
        atomicAdd(&d_stats[64+tid],   (double)(csq[tid]+v*v));
    }
}

// ---------------- finalize BN scale/shift + W_ih row sums -------------------
__global__ void k_bn(const float* __restrict__ gamma, const float* __restrict__ beta,
                     const float* __restrict__ wih) {
    int tid = threadIdx.x;
    if (tid < 64) {
        double n  = (double)BATCH*FEAT;
        double mu = d_stats[tid]/n;
        double var = d_stats[64+tid]/n - mu*mu;
        double sc = (double)gamma[tid] / sqrt(var + 1e-5);
        d_scale[tid] = (float)sc;
        d_shift[tid] = beta[tid] - (float)(mu*sc);
    }
    if (tid < 2*G3) {
        float s = 0.f;
        const float* w = wih + tid*FEAT;
        for (int f=0; f<FEAT; f++) s += w[f];
        d_wsum[tid] = s;
    }
}

// ---------------- GRU input gates: xg = scale*(W_ih·raw) + shift*wsum + b_ih
__global__ __launch_bounds__(256) void k_xg(const float* __restrict__ wih,
                                            const float* __restrict__ bih) {
    int z = blockIdx.z;            // dir*64 + s
    int dir = z >> 6, s = z & 63;
    int g0 = blockIdx.x*64, b0 = blockIdx.y*64;
    __shared__ float As[64][65];   // [m][f] raw feats
    __shared__ float Bs[64][65];   // [g][f] W_ih slice
    int tid = threadIdx.x;
    for (int i = tid; i < 64*65; i += 256) {
        int m = i/65, f = i - m*65;
        As[m][f] = (f < 64) ? d_HtH[((size_t)(b0+m)*64 + s)*64 + f]
                            : d_Hty[(b0+m)*64 + s];
    }
    const float* W = wih + dir*G3*FEAT;
    for (int i = tid; i < 64*65; i += 256) {
        int g = i/65, f = i - g*65;
        Bs[g][f] = W[(g0+g)*FEAT + f];
    }
    __syncthreads();
    int ty = tid >> 4, tx = tid & 15;
    float acc[4][4] = {};
#pragma unroll 5
    for (int k = 0; k < 65; k++) {
        float a[4], bb[4];
#pragma unroll
        for (int i=0;i<4;i++) a[i]  = As[ty*4+i][k];
#pragma unroll
        for (int j=0;j<4;j++) bb[j] = Bs[tx*4+j][k];
#pragma unroll
        for (int i=0;i<4;i++)
#pragma unroll
            for (int j=0;j<4;j++) acc[i][j] += a[i]*bb[j];
    }
    float sc = d_scale[s], sh = d_shift[s];
    size_t base = ((size_t)z*BATCH + b0)*G3;
    int g = g0 + tx*4;
    float w0 = sh*d_wsum[dir*G3+g+0] + bih[dir*G3+g+0];
    float w1 = sh*d_wsum[dir*G3+g+1] + bih[dir*G3+g+1];
    float w2 = sh*d_wsum[dir*G3+g+2] + bih[dir*G3+g+2];
    float w3 = sh*d_wsum[dir*G3+g+3] + bih[dir*G3+g+3];
#pragma unroll
    for (int i=0;i<4;i++) {
        int m = ty*4+i;
        float4 v;
        v.x = acc[i][0]*sc + w0;
        v.y = acc[i][1]*sc + w1;
        v.z = acc[i][2]*sc + w2;
        v.w = acc[i][3]*sc + w3;
        *reinterpret_cast<float4*>(&d_xg[base + (size_t)m*G3 + g]) = v;
    }
}

// ---------------- GRU per-step hidden GEMM: hg = h @ W_hh^T -----------------
__global__ __launch_bounds__(256) void k_gru_gemm(const float* __restrict__ whh, int ping) {
    int dir = blockIdx.z;
    int g0 = blockIdx.x*64, b0 = blockIdx.y*64;
    const float* hp = d_h[ping] + (size_t)dir*BATCH*HID;
    const float* W  = whh + dir*G3*HID;
    __shared__ float As[64][65];
    __shared__ float Bs[64][65];
    int tid = threadIdx.x;
    int ty = tid >> 4, tx = tid & 15;
    float acc[4][4] = {};
    for (int kc = 0; kc < 2; kc++) {
        __syncthreads();
        for (int i = tid; i < 4096; i += 256) {
            int m = i >> 6, kk = i & 63;
            As[m][kk] = hp[(size_t)(b0+m)*HID + kc*64 + kk];
            Bs[m][kk] = W[(size_t)(g0+m)*HID + kc*64 + kk];
        }
        __syncthreads();
#pragma unroll 8
        for (int k = 0; k < 64; k++) {
            float a[4], bb[4];
#pragma unroll
            for (int i=0;i<4;i++) a[i]  = As[ty*4+i][k];
#pragma unroll
            for (int j=0;j<4;j++) bb[j] = Bs[tx*4+j][k];
#pragma unroll
            for (int i=0;i<4;i++)
#pragma unroll
                for (int j=0;j<4;j++) acc[i][j] += a[i]*bb[j];
        }
    }
    float* outp = d_hg + (size_t)dir*BATCH*G3;
#pragma unroll
    for (int i=0;i<4;i++) {
        int m = b0 + ty*4 + i;
        float4 v = make_float4(acc[i][0],acc[i][1],acc[i][2],acc[i][3]);
        *reinterpret_cast<float4*>(&outp[(size_t)m*G3 + g0 + tx*4]) = v;
    }
}

// ---------------- GRU pointwise cell ----------------------------------------
__global__ __launch_bounds__(256) void k_gru_cell(const float* __restrict__ bhh,
                                                  int step, int ping) {
    int b = blockIdx.x;
    int tid = threadIdx.x;
    int dir = tid >> 7, j = tid & 127;
    int sx = dir ? (63 - step) : step;
    size_t xb = ((size_t)(dir*64 + sx)*BATCH + b)*G3;
    const float* hgb = d_hg + (size_t)dir*BATCH*G3 + (size_t)b*G3;
    const float* bh  = bhh + dir*G3;
    float xr = d_xg[xb + j], xz = d_xg[xb + 128 + j], xn = d_xg[xb + 256 + j];
    float hr = hgb[j]       + bh[j];
    float hz = hgb[128 + j] + bh[128 + j];
    float hn = hgb[256 + j] + bh[256 + j];
    float hprev = d_h[ping][(size_t)dir*BATCH*HID + b*HID + j];
    float r  = 1.f/(1.f + expf(-(xr+hr)));
    float zg = 1.f/(1.f + expf(-(xz+hz)));
    float n  = tanhf(xn + r*hn);
    float h  = (1.f - zg)*n + zg*hprev;
    d_h[1-ping][(size_t)dir*BATCH*HID + b*HID + j] = h;
    d_go[((size_t)b*64 + sx)*256 + dir*128 + j] = h;
}

// ---------------- w_x = go @ Wx^T -------------------------------------------
__global__ __launch_bounds__(256) void k_wx(const float* __restrict__ Wx) {
    int m0 = blockIdx.x*64;
    __shared__ float As[64][65];
    __shared__ float Bs[64][65];
    int tid = threadIdx.x;
    int ty = tid >> 4, tx = tid & 15;
    float acc[4][4] = {};
    for (int kc=0; kc<4; kc++) {
        __syncthreads();
        for (int i=tid;i<4096;i+=256) {
            int m = i>>6, kk = i&63;
            As[m][kk] = d_go[(size_t)(m0+m)*256 + kc*64 + kk];
            Bs[m][kk] = Wx[(size_t)m*256 + kc*64 + kk];
        }
        __syncthreads();
#pragma unroll 8
        for (int k = 0; k < 64; k++) {
            float a[4], bb[4];
#pragma unroll
            for (int i=0;i<4;i++) a[i]  = As[ty*4+i][k];
#pragma unroll
            for (int j=0;j<4;j++) bb[j] = Bs[tx*4+j][k];
#pragma unroll
            for (int i=0;i<4;i++)
#pragma unroll
                for (int j=0;j<4;j++) acc[i][j] += a[i]*bb[j];
        }
    }
#pragma unroll
    for (int i=0;i<4;i++) {
        int m = m0 + ty*4 + i;
        float4 v = make_float4(acc[i][0],acc[i][1],acc[i][2],acc[i][3]);
        *reinterpret_cast<float4*>(&d_wx[(size_t)m*64 + tx*4]) = v;
    }
}

// ---------------- gx[b,c] = sum_s go[b,s,c] * xhat[b,s] ---------------------
__global__ __launch_bounds__(256) void k_gx(const float* __restrict__ x_raw) {
    int b = blockIdx.x;
    int c = threadIdx.x;
    __shared__ float xh[64];
    if (c < 64) xh[c] = 2.f*x_raw[b*64+c] - 3.f;   // 2x - 2^RATE + 1, RATE=2
    __syncthreads();
    float acc = 0.f;
    const float* g = d_go + (size_t)b*64*256;
#pragma unroll 8
    for (int s=0;s<64;s++) acc += g[s*256+c]*xh[s];
    d_gx[(size_t)b*256 + c] = acc;
}

// ---------------- final per-batch: z0, GD loop, output ----------------------
__global__ __launch_bounds__(256) void k_final(const float* __restrict__ Wz,
                                               float* __restrict__ outp) {
    int b = blockIdx.x, tid = threadIdx.x;
    __shared__ float Ws[64][65];     // w_x[s][z]
    __shared__ float As[64][65];     // HtH
    __shared__ float hy[64], zv[64], wh[64], t1[64], t2[64];
    __shared__ float gxs[256];
    for (int i=tid;i<4096;i+=256) Ws[i>>6][i&63] = d_wx[(size_t)b*4096 + i];
    for (int i=tid;i<4096;i+=256) As[i>>6][i&63] = d_HtH[(size_t)b*4096 + i];
    if (tid<64) hy[tid] = d_Hty[b*64+tid];
    gxs[tid] = d_gx[(size_t)b*256 + tid];
    __syncthreads();
    if (tid<64) {
        float a=0.f;
        const float* wz = Wz + tid*256;
#pragma unroll 8
        for (int c=0;c<256;c++) a += wz[c]*gxs[c];
        zv[tid] = a;                                  // z0
        float w=0.f;
#pragma unroll
        for (int s=0;s<64;s++) w += Ws[s][tid]*hy[s];
        wh[tid] = w;                                  // wxt @ Hty
    }
    __syncthreads();
    for (int it=0; it<10; it++) {
        if (tid<64) { float a=0.f;
#pragma unroll
            for (int zc=0;zc<64;zc++) a += Ws[tid][zc]*zv[zc];
            t1[tid]=a; }
        __syncthreads();
        if (tid<64) { float a=0.f;
#pragma unroll
            for (int u=0;u<64;u++) a += As[tid][u]*t1[u];
            t2[tid]=a; }
        __syncthreads();
        if (tid<64) { float a=0.f;
#pragma unroll
            for (int s=0;s<64;s++) a += Ws[s][tid]*t2[s];
            zv[tid] += 2e-6f*(wh[tid]-a); }
        __syncthreads();
    }
    if (tid<64) {
        float a=0.f;
#pragma unroll
        for (int zc=0;zc<64;zc++) a += Ws[tid][zc]*zv[zc];
        outp[b*64+tid] = a;
    }
}

// ---------------- launch ----------------------------------------------------
extern "C" void kernel_launch(void* const* d_in, const int* in_sizes, int n_in,
                              void* d_out, int out_size) {
    const float* y     = (const float*)d_in[0];
    const float* H     = (const float*)d_in[1];
    const float* xraw  = (const float*)d_in[2];
    const float* wih   = (const float*)d_in[3];
    const float* whh   = (const float*)d_in[4];
    const float* bih   = (const float*)d_in[5];
    const float* bhh   = (const float*)d_in[6];
    const float* Wz    = (const float*)d_in[7];
    const float* Wx    = (const float*)d_in[8];
    const float* gamma = (const float*)d_in[9];
    const float* beta  = (const float*)d_in[10];
    float* outp = (float*)d_out;

    k_init<<<8192,256>>>();
    k_hth<<<BATCH,256>>>(H, y);
    k_bn<<<1,768>>>(gamma, beta, wih);
    dim3 gc(6,128,128);
    k_xg<<<gc,256>>>(wih, bih);
    for (int step=0; step<64; step++) {
        int ping = step & 1;
        dim3 gd(6,128,2);
        k_gru_gemm<<<gd,256>>>(whh, ping);
        k_gru_cell<<<BATCH,256>>>(bhh, step, ping);
    }
    k_wx<<<8192,256>>>(Wx);
    k_gx<<<BATCH,256>>>(xraw);
    k_final<<<BATCH,256>>>(Wz, outp);
}